// round 8
// baseline (speedup 1.0000x reference)
#include <cuda_runtime.h>
#include <cuda_bf16.h>
#include <cstdint>
#include <math.h>

// Shapes: support [5,196,384], query [512,196,384], out [1,512,5]
#define NC 5
#define M_IMG 512
#define P 196
#define D 384

#define NEG_BIG (-1.0e30f)

#define SROWS 256            // padded support rows per class in g_sbf (zero-init)
#define BR 208               // resident query rows (26 n8 tiles)
#define NT8 26               // query n8 tiles
#define NCH 7                // support chunks per class (6x32 + 1x16 = 208 rows)
#define GCH (NC * NCH)       // 35 global chunks

#define B_KT_STRIDE (BR * 128)   // 26624 B per k-tile (query)
#define A_KT_STRIDE 4096         // 32 rows * 128B per k-tile (support chunk)
#define A_BUF_SIZE 24576         // 32 rows * 768B

// smem: [0..896) pmax | [1024..160768) B query | [160768..209920) A bufs x2
#define SM_B 1024
#define SM_A 160768
#define SM_TOTAL 209920

#define THREADS 128

// ---------------- staged data (allocation-free: __device__ globals) -----------
// query: raw bf16 (+64 zero pad rows: resident reads reach row 207 for m=511)
__device__ __align__(16) __nv_bfloat16 g_qbf[(M_IMG * P + 64) * D];
// support: L2-normalized bf16, padded to 256 rows/class (pad rows stay zero)
__device__ __align__(16) __nv_bfloat16 g_sbf[NC * SROWS * D];
// inverse L2 norm of each query row
__device__ float g_invq[M_IMG * P];

// ---------------- PTX helpers -------------------------------------------------
__device__ __forceinline__ uint32_t smem_u32(const void* p) {
    uint32_t a;
    asm("{ .reg .u64 t; cvta.to.shared.u64 t, %1; cvt.u32.u64 %0, t; }" : "=r"(a) : "l"(p));
    return a;
}
#define SW128(o) ((o) ^ (((o) >> 3) & 0x70))

__device__ __forceinline__ void cp_async16(uint32_t dst, const void* src) {
    asm volatile("cp.async.cg.shared.global [%0], [%1], 16;" :: "r"(dst), "l"(src));
}
__device__ __forceinline__ void cp_commit() { asm volatile("cp.async.commit_group;" ::: "memory"); }
template <int N>
__device__ __forceinline__ void cp_wait_n() {
    asm volatile("cp.async.wait_group %0;" :: "n"(N) : "memory");
}

#define LDSM_X4(r, addr) \
    asm volatile("ldmatrix.sync.aligned.m8n8.x4.shared.b16 {%0,%1,%2,%3}, [%4];" \
        : "=r"((r)[0]), "=r"((r)[1]), "=r"((r)[2]), "=r"((r)[3]) : "r"(addr))

#define LDSM_X2(r0, r1, addr) \
    asm volatile("ldmatrix.sync.aligned.m8n8.x2.shared.b16 {%0,%1}, [%2];" \
        : "=r"(r0), "=r"(r1) : "r"(addr))

#define MMA16816(c, a, b0, b1) \
    asm volatile("mma.sync.aligned.m16n8k16.row.col.f32.bf16.bf16.f32 " \
        "{%0,%1,%2,%3}, {%4,%5,%6,%7}, {%8,%9}, {%0,%1,%2,%3};" \
        : "+f"((c)[0]), "+f"((c)[1]), "+f"((c)[2]), "+f"((c)[3]) \
        : "r"((a)[0]), "r"((a)[1]), "r"((a)[2]), "r"((a)[3]), "r"(b0), "r"(b1))

// ---------------- Kernel 1: norms + bf16 staging ------------------------------
__global__ void stage_kernel(const float* __restrict__ support,
                             const float* __restrict__ query) {
    const int warp = (blockIdx.x * blockDim.x + threadIdx.x) >> 5;
    const int lane = threadIdx.x & 31;
    const int nq = M_IMG * P;
    const int nrows = nq + NC * P;
    if (warp >= nrows) return;

    const bool is_q = (warp < nq);
    const float* src = is_q ? (query + (size_t)warp * D)
                            : (support + (size_t)(warp - nq) * D);

    float4 v[3];
    float s = 0.0f;
    #pragma unroll
    for (int j = 0; j < 3; ++j) {
        v[j] = reinterpret_cast<const float4*>(src)[lane + 32 * j];
        s += v[j].x * v[j].x + v[j].y * v[j].y + v[j].z * v[j].z + v[j].w * v[j].w;
    }
    #pragma unroll
    for (int off = 16; off; off >>= 1) s += __shfl_xor_sync(0xffffffffu, s, off);
    const float inv = 1.0f / fmaxf(sqrtf(s), 1e-12f);

    if (is_q) {
        uint32_t* dst = reinterpret_cast<uint32_t*>(g_qbf + (size_t)warp * D);
        #pragma unroll
        for (int j = 0; j < 3; ++j) {
            const int k = lane + 32 * j;
            __nv_bfloat162 a = __floats2bfloat162_rn(v[j].x, v[j].y);
            __nv_bfloat162 b = __floats2bfloat162_rn(v[j].z, v[j].w);
            dst[2 * k]     = *reinterpret_cast<uint32_t*>(&a);
            dst[2 * k + 1] = *reinterpret_cast<uint32_t*>(&b);
        }
        if (lane == 0) g_invq[warp] = inv;
    } else {
        const int sr = warp - nq;
        const int c = sr / P, p = sr % P;
        uint32_t* dst = reinterpret_cast<uint32_t*>(g_sbf + ((size_t)c * SROWS + p) * D);
        #pragma unroll
        for (int j = 0; j < 3; ++j) {
            const int k = lane + 32 * j;
            __nv_bfloat162 a = __floats2bfloat162_rn(v[j].x * inv, v[j].y * inv);
            __nv_bfloat162 b = __floats2bfloat162_rn(v[j].z * inv, v[j].w * inv);
            dst[2 * k]     = *reinterpret_cast<uint32_t*>(&a);
            dst[2 * k + 1] = *reinterpret_cast<uint32_t*>(&b);
        }
    }
}

// ---------------- Kernel 2: query-resident fused HMMA + max + top6 ------------
// CTA per query image m. A operand = streamed support chunk (m16 rows),
// B operand = resident query (n8 cols). C[s,q]; max over s folds in-register.
__global__ __launch_bounds__(THREADS, 1)
void protonet_hmma_kernel(const float* __restrict__ scale_cls,
                          const float* __restrict__ bias,
                          float* __restrict__ out) {
    extern __shared__ char sm[];
    const uint32_t smb = smem_u32(sm);
    float* pmax = reinterpret_cast<float*>(sm);    // [224] per class, reused
    const int tid = threadIdx.x;
    const int w = tid >> 5;
    const int lane = tid & 31;
    const int m = blockIdx.x;

    const __nv_bfloat16* qbase = g_qbf + (size_t)m * P * D;
    const float* invq = g_invq + (size_t)m * P;

    // support chunk loader: global chunk g -> class g/7, chunk g%7; buf in {0,1}
    auto stage_s = [&](int g, int buf) {
        const int cls = g / NCH;
        const int ch = g - cls * NCH;
        const int rows = (ch == 6) ? 16 : 32;
        const __nv_bfloat16* sbase = g_sbf + ((size_t)cls * SROWS + ch * 32) * D;
        const uint32_t abase = smb + SM_A + buf * A_BUF_SIZE;
        const int n16 = rows * 8 * 6;
        for (int idx = tid; idx < n16; idx += THREADS) {
            const int kt  = idx / (rows * 8);
            const int rem = idx - kt * (rows * 8);
            const int row = rem >> 3;
            const int cb  = (rem & 7) << 4;
            const void* src = sbase + (size_t)row * D + kt * 64 + (cb >> 1);
            cp_async16(abase + kt * A_KT_STRIDE + SW128(row * 128 + cb), src);
        }
    };

    // prologue: resident query B (208 rows x 384), then support chunk 0
    for (int idx = tid; idx < BR * 8 * 6; idx += THREADS) {   // 9984 x 16B
        const int kt  = idx / (BR * 8);
        const int rem = idx - kt * (BR * 8);
        const int row = rem >> 3;
        const int cb  = (rem & 7) << 4;
        const void* src = qbase + (size_t)row * D + kt * 64 + (cb >> 1);
        cp_async16(smb + SM_B + kt * B_KT_STRIDE + SW128(row * 128 + cb), src);
    }
    cp_commit();
    stage_s(0, 0);
    cp_commit();

    // lane-derived LDSM addressing
    const int l7 = lane & 7;
    const int a_row = (((lane >> 3) & 1) << 3) + l7;   // support m16 fragment row
    const int a_kb  = ((lane >> 4) & 1) << 4;
    const int sel16 = ((lane >> 3) & 1) << 4;          // query x2: +16B for k 8..15

    // per-warp n8 tiles: t = w + 4i (i<7), valid while t < 26 (warp-uniform)
    float rmax[7][2];
    #pragma unroll
    for (int i = 0; i < 7; ++i) { rmax[i][0] = NEG_BIG; rmax[i][1] = NEG_BIG; }

    for (int g = 0; g < GCH; ++g) {
        if (g) __syncthreads();                 // compute g-1 done -> buf (g+1)&1 free
        if (g + 1 < GCH) {
            stage_s(g + 1, (g + 1) & 1);
            cp_commit();
            cp_wait_n<1>();                     // chunk g (+ B at g=0) arrived
        } else {
            cp_wait_n<0>();
        }
        __syncthreads();

        const uint32_t abase_ = smb + SM_A + (g & 1) * A_BUF_SIZE;
        const uint32_t bbase_ = smb + SM_B;
        const int ch = g % NCH;
        const int MT = (ch == 6) ? 1 : 2;       // tail chunk: 1 m16 (rows 192-207)

        float cacc[2][7][4];
        #pragma unroll
        for (int i = 0; i < 2; ++i)
            #pragma unroll
            for (int j = 0; j < 7; ++j)
                #pragma unroll
                for (int k = 0; k < 4; ++k) cacc[i][j][k] = 0.0f;

        for (int kt = 0; kt < 6; ++kt) {
            const uint32_t abase = abase_ + kt * A_KT_STRIDE;
            const uint32_t bbase = bbase_ + kt * B_KT_STRIDE;
            #pragma unroll
            for (int k16 = 0; k16 < 4; ++k16) {
                const int kb = k16 * 32;
                uint32_t a[2][4];
                LDSM_X4(a[0], abase + SW128(a_row * 128 + kb + a_kb));
                if (MT == 2)
                    LDSM_X4(a[1], abase + SW128((16 + a_row) * 128 + kb + a_kb));
                uint32_t b[7][2];
                #pragma unroll
                for (int i = 0; i < 7; ++i) {
                    const int t = w + 4 * i;
                    if (t < NT8)
                        LDSM_X2(b[i][0], b[i][1],
                                bbase + SW128((t * 8 + l7) * 128 + kb + sel16));
                }
                #pragma unroll
                for (int i = 0; i < 7; ++i) {
                    if (w + 4 * i < NT8) {
                        MMA16816(cacc[0][i], a[0], b[i][0], b[i][1]);
                        if (MT == 2)
                            MMA16816(cacc[1][i], a[1], b[i][0], b[i][1]);
                    }
                }
            }
        }

        // fold support-row max into per-lane running max
        if (MT == 2) {
            #pragma unroll
            for (int i = 0; i < 7; ++i) {
                if (w + 4 * i < NT8) {
                    rmax[i][0] = fmaxf(rmax[i][0],
                        fmaxf(fmaxf(cacc[0][i][0], cacc[0][i][2]),
                              fmaxf(cacc[1][i][0], cacc[1][i][2])));
                    rmax[i][1] = fmaxf(rmax[i][1],
                        fmaxf(fmaxf(cacc[0][i][1], cacc[0][i][3]),
                              fmaxf(cacc[1][i][1], cacc[1][i][3])));
                }
            }
        } else {
            // tail tile rows 192-207: c0/c1 row = 192+(lane>>2) valid iff lane<16;
            // c2/c3 rows 200+ never valid
            if (lane < 16) {
                #pragma unroll
                for (int i = 0; i < 7; ++i) {
                    if (w + 4 * i < NT8) {
                        rmax[i][0] = fmaxf(rmax[i][0], cacc[0][i][0]);
                        rmax[i][1] = fmaxf(rmax[i][1], cacc[0][i][1]);
                    }
                }
            }
        }

        if (ch == 6) {
            // ---- class end: reduce across fragment-row lanes, write pmax ----
            const int cls = g / NCH;
            #pragma unroll
            for (int i = 0; i < 7; ++i) {
                const int t = w + 4 * i;
                if (t < NT8) {
                    float v0 = rmax[i][0], v1 = rmax[i][1];
                    #pragma unroll
                    for (int off = 4; off <= 16; off <<= 1) {
                        v0 = fmaxf(v0, __shfl_xor_sync(0xffffffffu, v0, off));
                        v1 = fmaxf(v1, __shfl_xor_sync(0xffffffffu, v1, off));
                    }
                    if (lane < 4) {
                        const int q0 = t * 8 + 2 * lane;
                        if (q0 < P)     pmax[q0]     = v0 * invq[q0];
                        if (q0 + 1 < P) pmax[q0 + 1] = v1 * invq[q0 + 1];
                    }
                    rmax[i][0] = NEG_BIG; rmax[i][1] = NEG_BIG;
                }
            }
            __syncthreads();

            // warp 0: exact top-6 over pmax[0..195]
            if (w == 0) {
                float v[7];
                #pragma unroll
                for (int k = 0; k < 7; ++k) {
                    const int p = lane + 32 * k;
                    v[k] = (p < P) ? pmax[p] : NEG_BIG;
                }
                float total = 0.0f;
                for (int it = 0; it < 6; ++it) {
                    float bv = NEG_BIG; int bk = 0;
                    #pragma unroll
                    for (int k = 0; k < 7; ++k)
                        if (v[k] > bv) { bv = v[k]; bk = k; }
                    int bi = lane + 32 * bk;
                    #pragma unroll
                    for (int off = 16; off; off >>= 1) {
                        float ov = __shfl_xor_sync(0xffffffffu, bv, off);
                        int   oi = __shfl_xor_sync(0xffffffffu, bi, off);
                        if (ov > bv || (ov == bv && oi < bi)) { bv = ov; bi = oi; }
                    }
                    total += bv;
                    if ((bi & 31) == lane) v[bi >> 5] = NEG_BIG;
                }
                if (lane == 0) out[m * NC + cls] = scale_cls[0] * (total + bias[0]);
            }
        }
    }
}

// ---------------------------------------------------------------------------
extern "C" void kernel_launch(void* const* d_in, const int* in_sizes, int n_in,
                              void* d_out, int out_size) {
    const float* support   = (const float*)d_in[0];
    const float* query     = (const float*)d_in[1];
    const float* scale_cls = (const float*)d_in[2];
    const float* bias      = (const float*)d_in[3];
    float* out = (float*)d_out;

    // Stage 1: norms + bf16 conversion
    const int nrows = M_IMG * P + NC * P;
    const int blocks = (nrows * 32 + 255) / 256;
    stage_kernel<<<blocks, 256>>>(support, query);

    // Stage 2: fused HMMA GEMM + reductions (set attribute every call; capture-safe)
    cudaFuncSetAttribute(protonet_hmma_kernel,
                         cudaFuncAttributeMaxDynamicSharedMemorySize, SM_TOTAL);
    protonet_hmma_kernel<<<M_IMG, THREADS, SM_TOTAL>>>(scale_cls, bias, out);
}